// round 6
// baseline (speedup 1.0000x reference)
#include <cuda_runtime.h>
#include <math.h>

// Problem shape (fixed by setup_inputs)
#define NB 2
#define LL 2048
#define HH 8
#define DD 64
#define MM 64
#define NH (NB*HH)          // 16
#define T  32               // chunk length (halved vs R1 for 2x grid parallelism)
#define CC (LL/T)           // 64 chunks
#define NBLK (NH*CC)        // 1024
#define EPSF 1e-6f

// Scratch: per (head, chunk) partial sums. Static device arrays (no runtime alloc).
__device__ float g_S[(size_t)NH*CC*DD*MM];   // 16.8 MB
__device__ float g_k[(size_t)NH*CC*DD];      // 256 KB

__device__ __forceinline__ float phi(float x) {
    return x > 0.0f ? x + 1.0f : expf(x);   // elu(x)+1
}
__device__ __forceinline__ float4 phi4(float4 a) {
    return make_float4(phi(a.x), phi(a.y), phi(a.z), phi(a.w));
}

// ---------------------------------------------------------------------------
// Kernel A: per-chunk sums  Schunk[d][m] = sum_t phi(k)[t][d] * v[t][m]
// grid = 1024 blocks (nh, c), 256 threads: thread (m, dq) owns 16 d-rows.
// ---------------------------------------------------------------------------
__global__ void __launch_bounds__(256) chunk_sums_kernel(
    const float* __restrict__ keys, const float* __restrict__ values)
{
    __shared__ float Ks[T*DD];   // 8 KB
    __shared__ float Vs[T*MM];   // 8 KB

    const int b   = blockIdx.x;
    const int nh  = b / CC, c = b % CC;
    const int n   = nh / HH, h = nh % HH;
    const int tid = threadIdx.x;

    const float4* kg = (const float4*)keys;
    const float4* vg = (const float4*)values;
    float4* Ks4 = (float4*)Ks;
    float4* Vs4 = (float4*)Vs;

    #pragma unroll
    for (int f = tid; f < T*DD/4; f += 256) {
        int t = f >> 4, d4 = f & 15;
        int gi = ((n*LL + c*T + t)*HH + h)*(DD/4) + d4;
        Ks4[f] = phi4(kg[gi]);
        Vs4[f] = vg[gi];
    }
    __syncthreads();

    const int dq = tid & 3;     // quarter of D
    const int m  = tid >> 2;    // output column

    float acc[16];
    #pragma unroll
    for (int j = 0; j < 16; j++) acc[j] = 0.0f;

    const float4* KK = (const float4*)Ks;
    for (int t = 0; t < T; t++) {
        float v = Vs[t*MM + m];
        #pragma unroll
        for (int jj = 0; jj < 4; jj++) {
            float4 k4 = KK[t*16 + dq*4 + jj];
            acc[jj*4+0] += k4.x * v;
            acc[jj*4+1] += k4.y * v;
            acc[jj*4+2] += k4.z * v;
            acc[jj*4+3] += k4.w * v;
        }
    }

    float* So = &g_S[(size_t)b * DD * MM];
    #pragma unroll
    for (int j = 0; j < 16; j++)
        So[(dq*16 + j)*MM + m] = acc[j];

    if (tid < DD) {
        float s = 0.0f;
        #pragma unroll
        for (int t = 0; t < T; t++) s += Ks[t*DD + tid];
        g_k[(size_t)b*DD + tid] = s;
    }
}

// ---------------------------------------------------------------------------
// Kernel B: in-place exclusive prefix over chunks.
// blocks [0, NH*DD): one (nh,d) row of S, 64 threads (one per m), all 64
//   chunk values register-resident (independent loads -> full MLP).
// blocks [NH*DD, NH*DD+NH): k rows, thread d per column.
// ---------------------------------------------------------------------------
__global__ void __launch_bounds__(64) prefix_kernel()
{
    const int blk = blockIdx.x;
    const int tid = threadIdx.x;

    if (blk < NH*DD) {
        const int nh = blk / DD, d = blk % DD;
        float* base = g_S + ((size_t)nh*CC*DD + d)*MM + tid;   // +c*DD*MM per chunk

        float val[CC];
        #pragma unroll
        for (int c = 0; c < CC; c++) val[c] = base[(size_t)c*DD*MM];
        float run = 0.0f;
        #pragma unroll
        for (int c = 0; c < CC; c++) {
            base[(size_t)c*DD*MM] = run;
            run += val[c];
        }
    } else {
        const int nh = blk - NH*DD;
        float* base = g_k + (size_t)nh*CC*DD + tid;            // +c*DD per chunk

        float val[CC];
        #pragma unroll
        for (int c = 0; c < CC; c++) val[c] = base[c*DD];
        float run = 0.0f;
        #pragma unroll
        for (int c = 0; c < CC; c++) {
            base[c*DD] = run;
            run += val[c];
        }
    }
}

// ---------------------------------------------------------------------------
// Kernel C: in-chunk sequential scan, register-resident state.
// grid = 1024 blocks, 256 threads: thread (m, dq) owns S[dq*16..+15][m].
// ---------------------------------------------------------------------------
__global__ void __launch_bounds__(256) scan_kernel(
    const float* __restrict__ queries, const float* __restrict__ keys,
    const float* __restrict__ values, float* __restrict__ out)
{
    __shared__ float Qs[T*DD];     // 8 KB
    __shared__ float Ks[T*DD];     // 8 KB
    __shared__ float Vs[T*MM];     // 8 KB
    __shared__ float kcum[T*DD];   // 8 KB
    __shared__ float zinv[T];
    __shared__ float kpre[DD];

    const int b   = blockIdx.x;
    const int nh  = b / CC, c = b % CC;
    const int n   = nh / HH, h = nh % HH;
    const int tid = threadIdx.x;

    const float4* qg = (const float4*)queries;
    const float4* kg = (const float4*)keys;
    const float4* vg = (const float4*)values;
    float4* Qs4 = (float4*)Qs;
    float4* Ks4 = (float4*)Ks;
    float4* Vs4 = (float4*)Vs;

    #pragma unroll
    for (int f = tid; f < T*DD/4; f += 256) {
        int t = f >> 4, d4 = f & 15;
        int gi = ((n*LL + c*T + t)*HH + h)*(DD/4) + d4;
        Qs4[f] = phi4(qg[gi]);
        Ks4[f] = phi4(kg[gi]);
        Vs4[f] = vg[gi];
    }
    if (tid < DD) kpre[tid] = g_k[(size_t)b*DD + tid];
    __syncthreads();

    // inclusive kcum per d (threads 0..63)
    if (tid < DD) {
        float kc = kpre[tid];
        #pragma unroll
        for (int i = 0; i < T; i++) {
            kc += Ks[i*DD + tid];
            kcum[i*DD + tid] = kc;
        }
    }
    __syncthreads();

    // zinv[i] = 1/(phi(q_i).kcum_i + eps)  (threads 0..31)
    if (tid < T) {
        const float4* qr = (const float4*)&Qs[tid*DD];
        const float4* kr = (const float4*)&kcum[tid*DD];
        float z = 0.0f;
        #pragma unroll
        for (int d4 = 0; d4 < 16; d4++) {
            float4 a = qr[d4], bb = kr[d4];
            z += a.x*bb.x + a.y*bb.y + a.z*bb.z + a.w*bb.w;
        }
        zinv[tid] = 1.0f / (z + EPSF);
    }
    __syncthreads();

    const int dq = tid & 3;
    const int m  = tid >> 2;

    float acc[16];
    const float* Sp = &g_S[(size_t)b * DD * MM];
    #pragma unroll
    for (int j = 0; j < 16; j++)
        acc[j] = Sp[(dq*16 + j)*MM + m];

    const float4* KK = (const float4*)Ks;
    const float4* QQ = (const float4*)Qs;
    const int obase = ((n*LL + c*T)*HH + h)*MM + m;

    for (int i = 0; i < T; i++) {
        float vv = Vs[i*MM + m];
        float p0 = 0.f, p1 = 0.f, p2 = 0.f, p3 = 0.f;
        #pragma unroll
        for (int jj = 0; jj < 4; jj++) {
            float4 k4 = KK[i*16 + dq*4 + jj];
            float4 q4 = QQ[i*16 + dq*4 + jj];
            acc[jj*4+0] += k4.x * vv;  p0 += q4.x * acc[jj*4+0];
            acc[jj*4+1] += k4.y * vv;  p1 += q4.y * acc[jj*4+1];
            acc[jj*4+2] += k4.z * vv;  p2 += q4.z * acc[jj*4+2];
            acc[jj*4+3] += k4.w * vv;  p3 += q4.w * acc[jj*4+3];
        }
        float p = (p0 + p1) + (p2 + p3);
        // reduce over the 4 d-quarters (adjacent lanes)
        p += __shfl_xor_sync(0xffffffffu, p, 1);
        p += __shfl_xor_sync(0xffffffffu, p, 2);
        if (dq == 0)
            out[obase + i*HH*MM] = p * zinv[i];
    }
}

// ---------------------------------------------------------------------------
extern "C" void kernel_launch(void* const* d_in, const int* in_sizes, int n_in,
                              void* d_out, int out_size)
{
    const float* queries = (const float*)d_in[0];
    const float* keys    = (const float*)d_in[1];
    const float* values  = (const float*)d_in[2];
    float* out = (float*)d_out;

    chunk_sums_kernel<<<NBLK, 256>>>(keys, values);
    prefix_kernel<<<NH*DD + NH, 64>>>();
    scan_kernel<<<NBLK, 256>>>(queries, keys, values, out);
}

// round 7
// speedup vs baseline: 1.7355x; 1.7355x over previous
#include <cuda_runtime.h>
#include <math.h>

// Problem shape (fixed by setup_inputs)
#define NB 2
#define LL 2048
#define HH 8
#define DD 64
#define MM 64
#define NH (NB*HH)          // 16
#define T  64               // chunk length
#define CC (LL/T)           // 32 chunks
#define NBLK (NH*CC)        // 512
#define EPSF 1e-6f

// Scratch (static device arrays — no runtime alloc)
__device__ float g_S[(size_t)NH*CC*DD*MM];   // 8.4 MB
__device__ float g_k[(size_t)NH*CC*DD];      // 128 KB

__device__ __forceinline__ float phi(float x) {
    return x > 0.0f ? x + 1.0f : expf(x);   // elu(x)+1
}
__device__ __forceinline__ float4 phi4(float4 a) {
    return make_float4(phi(a.x), phi(a.y), phi(a.z), phi(a.w));
}

// ---------------------------------------------------------------------------
// Kernel A: chunk sums  Sc[d][m] = sum_t phi(k)[t][d] * v[t][m]
// 512 blocks, 256 threads. 4x4 register tile: thread (td,tm) owns
// S[4td..4td+3][4tm..4tm+3]. Per t: 2 LDS.128 (conflict-free) + 16 FFMA.
// ---------------------------------------------------------------------------
__global__ void __launch_bounds__(256) chunk_sums_kernel(
    const float* __restrict__ keys, const float* __restrict__ values)
{
    __shared__ float Ks[T*DD];     // 16 KB
    __shared__ float Vs[T*MM];     // 16 KB
    __shared__ float seg[4*DD];    // 1 KB (ksum partials)

    const int b   = blockIdx.x;
    const int nh  = b / CC, c = b % CC;
    const int n   = nh / HH, h = nh % HH;
    const int tid = threadIdx.x;

    const float4* kg = (const float4*)keys;
    const float4* vg = (const float4*)values;
    float4* Ks4 = (float4*)Ks;
    float4* Vs4 = (float4*)Vs;

    #pragma unroll
    for (int f = tid; f < T*DD/4; f += 256) {
        int t = f >> 4, d4 = f & 15;
        int gi = ((n*LL + c*T + t)*HH + h)*(DD/4) + d4;
        Ks4[f] = phi4(kg[gi]);
        Vs4[f] = vg[gi];
    }
    __syncthreads();

    const int td = tid >> 4;    // 0..15 (warp has 2 distinct td -> broadcast k4)
    const int tm = tid & 15;    // 0..15

    float acc[16];
    #pragma unroll
    for (int j = 0; j < 16; j++) acc[j] = 0.0f;

    const float4* K4 = (const float4*)Ks;
    const float4* V4 = (const float4*)Vs;
    #pragma unroll 4
    for (int t = 0; t < T; t++) {
        float4 k4 = K4[t*16 + td];
        float4 v4 = V4[t*16 + tm];
        acc[ 0] += k4.x*v4.x; acc[ 1] += k4.x*v4.y; acc[ 2] += k4.x*v4.z; acc[ 3] += k4.x*v4.w;
        acc[ 4] += k4.y*v4.x; acc[ 5] += k4.y*v4.y; acc[ 6] += k4.y*v4.z; acc[ 7] += k4.y*v4.w;
        acc[ 8] += k4.z*v4.x; acc[ 9] += k4.z*v4.y; acc[10] += k4.z*v4.z; acc[11] += k4.z*v4.w;
        acc[12] += k4.w*v4.x; acc[13] += k4.w*v4.y; acc[14] += k4.w*v4.z; acc[15] += k4.w*v4.w;
    }

    float* So = &g_S[(size_t)b * DD * MM];
    #pragma unroll
    for (int r = 0; r < 4; r++) {
        float4 o = make_float4(acc[r*4+0], acc[r*4+1], acc[r*4+2], acc[r*4+3]);
        *(float4*)&So[(4*td + r)*MM + 4*tm] = o;
    }

    // ksum[d] via 4 segment partials (all 256 threads busy)
    {
        const int d = tid & 63, q = tid >> 6;
        float s = 0.0f;
        #pragma unroll
        for (int i = q*16; i < q*16 + 16; i++) s += Ks[i*DD + d];
        seg[q*DD + d] = s;
    }
    __syncthreads();
    if (tid < DD) {
        g_k[(size_t)b*DD + tid] =
            seg[tid] + seg[DD + tid] + seg[2*DD + tid] + seg[3*DD + tid];
    }
}

// ---------------------------------------------------------------------------
// Kernel B: in-place exclusive prefix over chunks (32 values in registers).
// blocks [0,1024): one (nh,d) row of S, 64 threads (one per m).
// blocks [1024,1040): g_k rows.
// ---------------------------------------------------------------------------
__global__ void __launch_bounds__(64) prefix_kernel()
{
    const int blk = blockIdx.x;
    const int tid = threadIdx.x;

    if (blk < NH*DD) {
        const int nh = blk >> 6, d = blk & 63;
        float* base = g_S + ((size_t)nh*CC*DD + d)*MM + tid;   // + c*DD*MM per chunk
        float val[CC];
        #pragma unroll
        for (int c = 0; c < CC; c++) val[c] = base[(size_t)c*DD*MM];
        float run = 0.0f;
        #pragma unroll
        for (int c = 0; c < CC; c++) {
            base[(size_t)c*DD*MM] = run;
            run += val[c];
        }
    } else {
        const int nh = blk - NH*DD;
        float* base = g_k + (size_t)nh*CC*DD + tid;
        float val[CC];
        #pragma unroll
        for (int c = 0; c < CC; c++) val[c] = base[c*DD];
        float run = 0.0f;
        #pragma unroll
        for (int c = 0; c < CC; c++) {
            base[c*DD] = run;
            run += val[c];
        }
    }
}

// ---------------------------------------------------------------------------
// Kernel C: in-chunk sequential scan, register-resident state.
// 512 blocks, 256 threads. Thread (dq,m): owns interleaved d-set
//   d = 16*jj + 4*dq + e   (jj=0..3, e=0..3)  -> conflict-free LDS.128.
// z precomputed via segmented cumsum + padded (stride-65) product scratch.
// ---------------------------------------------------------------------------
#define ZP_STRIDE 65
__global__ void __launch_bounds__(256) scan_kernel(
    const float* __restrict__ queries, const float* __restrict__ keys,
    const float* __restrict__ values, float* __restrict__ out)
{
    extern __shared__ float sm[];
    float* Qs   = sm;                          // 4096
    float* Ks   = sm + T*DD;                   // 4096
    float* Vs   = sm + 2*T*DD;                 // 4096
    float* zp   = sm + 3*T*DD;                 // 64*65 = 4160 (padded products)
    float* seg  = zp + T*ZP_STRIDE;            // 256
    float* zinv = seg + 4*DD;                  // 64
    float* kpre = zinv + T;                    // 64

    const int b   = blockIdx.x;
    const int nh  = b / CC, c = b % CC;
    const int n   = nh / HH, h = nh % HH;
    const int tid = threadIdx.x;

    const float4* qg = (const float4*)queries;
    const float4* kg = (const float4*)keys;
    const float4* vg = (const float4*)values;
    float4* Qs4 = (float4*)Qs;
    float4* Ks4 = (float4*)Ks;
    float4* Vs4 = (float4*)Vs;

    #pragma unroll
    for (int f = tid; f < T*DD/4; f += 256) {
        int t = f >> 4, d4 = f & 15;
        int gi = ((n*LL + c*T + t)*HH + h)*(DD/4) + d4;
        Qs4[f] = phi4(qg[gi]);
        Ks4[f] = phi4(kg[gi]);
        Vs4[f] = vg[gi];
    }
    if (tid < DD) kpre[tid] = g_k[(size_t)b*DD + tid];
    __syncthreads();

    // --- z phase: segmented cumsum of K along i, fused product with Q ---
    {
        const int d = tid & 63, q = tid >> 6;   // 4 i-segments of 16
        float s = 0.0f;
        #pragma unroll
        for (int i = q*16; i < q*16 + 16; i++) s += Ks[i*DD + d];
        seg[q*DD + d] = s;
        __syncthreads();
        float kc = kpre[d];
        #pragma unroll
        for (int r = 0; r < 4; r++) if (r < q) kc += seg[r*DD + d];
        #pragma unroll
        for (int i = q*16; i < q*16 + 16; i++) {
            kc += Ks[i*DD + d];
            zp[i*ZP_STRIDE + d] = Qs[i*DD + d] * kc;   // stride-65: conflict-free
        }
    }
    __syncthreads();
    if (tid < T) {
        float z = EPSF;
        #pragma unroll
        for (int d = 0; d < DD; d++) z += zp[tid*ZP_STRIDE + d];  // banks (tid+d)%32
        zinv[tid] = 1.0f / z;
    }
    __syncthreads();

    // --- main scan: thread (dq, m) owns S[16*jj+4*dq+e][m] ---
    const int dq = tid & 3;
    const int m  = tid >> 2;

    float acc[16];
    const float* Sp = &g_S[(size_t)b * DD * MM];
    #pragma unroll
    for (int jj = 0; jj < 4; jj++)
        #pragma unroll
        for (int e = 0; e < 4; e++)
            acc[jj*4+e] = Sp[(16*jj + 4*dq + e)*MM + m];

    const float4* K4 = (const float4*)Ks;
    const float4* Q4 = (const float4*)Qs;
    const int obase = ((n*LL + c*T)*HH + h)*MM + m;

    #pragma unroll 2
    for (int i = 0; i < T; i++) {
        float vv = Vs[i*MM + m];
        float p0 = 0.f, p1 = 0.f, p2 = 0.f, p3 = 0.f;
        {
            float4 k4 = K4[i*16 + 0*4 + dq];   // banks 4*dq -> conflict-free
            float4 q4 = Q4[i*16 + 0*4 + dq];
            acc[ 0] += k4.x*vv; p0 += q4.x*acc[ 0];
            acc[ 1] += k4.y*vv; p0 += q4.y*acc[ 1];
            acc[ 2] += k4.z*vv; p0 += q4.z*acc[ 2];
            acc[ 3] += k4.w*vv; p0 += q4.w*acc[ 3];
        }
        {
            float4 k4 = K4[i*16 + 1*4 + dq];
            float4 q4 = Q4[i*16 + 1*4 + dq];
            acc[ 4] += k4.x*vv; p1 += q4.x*acc[ 4];
            acc[ 5] += k4.y*vv; p1 += q4.y*acc[ 5];
            acc[ 6] += k4.z*vv; p1 += q4.z*acc[ 6];
            acc[ 7] += k4.w*vv; p1 += q4.w*acc[ 7];
        }
        {
            float4 k4 = K4[i*16 + 2*4 + dq];
            float4 q4 = Q4[i*16 + 2*4 + dq];
            acc[ 8] += k4.x*vv; p2 += q4.x*acc[ 8];
            acc[ 9] += k4.y*vv; p2 += q4.y*acc[ 9];
            acc[10] += k4.z*vv; p2 += q4.z*acc[10];
            acc[11] += k4.w*vv; p2 += q4.w*acc[11];
        }
        {
            float4 k4 = K4[i*16 + 3*4 + dq];
            float4 q4 = Q4[i*16 + 3*4 + dq];
            acc[12] += k4.x*vv; p3 += q4.x*acc[12];
            acc[13] += k4.y*vv; p3 += q4.y*acc[13];
            acc[14] += k4.z*vv; p3 += q4.z*acc[14];
            acc[15] += k4.w*vv; p3 += q4.w*acc[15];
        }
        float p = (p0 + p1) + (p2 + p3);
        p += __shfl_xor_sync(0xffffffffu, p, 1);   // reduce over dq (bits 0-1)
        p += __shfl_xor_sync(0xffffffffu, p, 2);
        if (dq == 0)
            out[obase + i*HH*MM] = p * zinv[i];
    }
}

// ---------------------------------------------------------------------------
extern "C" void kernel_launch(void* const* d_in, const int* in_sizes, int n_in,
                              void* d_out, int out_size)
{
    const float* queries = (const float*)d_in[0];
    const float* keys    = (const float*)d_in[1];
    const float* values  = (const float*)d_in[2];
    float* out = (float*)d_out;

    const int smem_scan =
        (3*T*DD + T*ZP_STRIDE + 4*DD + T + DD) * (int)sizeof(float);  // ~66 KB
    cudaFuncSetAttribute(scan_kernel,
                         cudaFuncAttributeMaxDynamicSharedMemorySize, smem_scan);

    chunk_sums_kernel<<<NBLK, 256>>>(keys, values);
    prefix_kernel<<<NH*DD + NH, 64>>>();
    scan_kernel<<<NBLK, 256, smem_scan>>>(queries, keys, values, out);
}

// round 9
// speedup vs baseline: 1.8793x; 1.0828x over previous
#include <cuda_runtime.h>
#include <math.h>

// Problem shape (fixed by setup_inputs)
#define NB 2
#define LL 2048
#define HH 8
#define DD 64
#define MM 64
#define NH (NB*HH)          // 16
#define T  32               // chunk length
#define CC (LL/T)           // 64 chunks
#define NBLK (NH*CC)        // 1024
#define EPSF 1e-6f

// Scratch (static device arrays — no runtime alloc)
__device__ float g_S[(size_t)NH*CC*DD*MM];   // 16.8 MB
__device__ float g_k[(size_t)NH*CC*DD];      // 256 KB

__device__ __forceinline__ float phi(float x) {
    return x > 0.0f ? x + 1.0f : expf(x);   // elu(x)+1
}
__device__ __forceinline__ float4 phi4(float4 a) {
    return make_float4(phi(a.x), phi(a.y), phi(a.z), phi(a.w));
}

// ---------------------------------------------------------------------------
// Kernel A: chunk sums  Sc[d][m] = sum_t phi(k)[t][d] * v[t][m]
// 1024 blocks, 256 threads. 4x4 register tile (conflict-free LDS.128).
// ---------------------------------------------------------------------------
__global__ void __launch_bounds__(256) chunk_sums_kernel(
    const float* __restrict__ keys, const float* __restrict__ values)
{
    __shared__ float Ks[T*DD];     // 8 KB
    __shared__ float Vs[T*MM];     // 8 KB
    __shared__ float seg[4*DD];    // 1 KB

    const int b   = blockIdx.x;
    const int nh  = b / CC, c = b % CC;
    const int n   = nh / HH, h = nh % HH;
    const int tid = threadIdx.x;

    const float4* kg = (const float4*)keys;
    const float4* vg = (const float4*)values;
    float4* Ks4 = (float4*)Ks;
    float4* Vs4 = (float4*)Vs;

    #pragma unroll
    for (int f = tid; f < T*DD/4; f += 256) {
        int t = f >> 4, d4 = f & 15;
        int gi = ((n*LL + c*T + t)*HH + h)*(DD/4) + d4;
        Ks4[f] = phi4(kg[gi]);
        Vs4[f] = vg[gi];
    }
    __syncthreads();

    const int td = tid >> 4;    // 0..15
    const int tm = tid & 15;    // 0..15

    float acc[16];
    #pragma unroll
    for (int j = 0; j < 16; j++) acc[j] = 0.0f;

    const float4* K4 = (const float4*)Ks;
    const float4* V4 = (const float4*)Vs;
    #pragma unroll 4
    for (int t = 0; t < T; t++) {
        float4 k4 = K4[t*16 + td];
        float4 v4 = V4[t*16 + tm];
        acc[ 0] += k4.x*v4.x; acc[ 1] += k4.x*v4.y; acc[ 2] += k4.x*v4.z; acc[ 3] += k4.x*v4.w;
        acc[ 4] += k4.y*v4.x; acc[ 5] += k4.y*v4.y; acc[ 6] += k4.y*v4.z; acc[ 7] += k4.y*v4.w;
        acc[ 8] += k4.z*v4.x; acc[ 9] += k4.z*v4.y; acc[10] += k4.z*v4.z; acc[11] += k4.z*v4.w;
        acc[12] += k4.w*v4.x; acc[13] += k4.w*v4.y; acc[14] += k4.w*v4.z; acc[15] += k4.w*v4.w;
    }

    float* So = &g_S[(size_t)b * DD * MM];
    #pragma unroll
    for (int r = 0; r < 4; r++) {
        float4 o = make_float4(acc[r*4+0], acc[r*4+1], acc[r*4+2], acc[r*4+3]);
        *(float4*)&So[(4*td + r)*MM + 4*tm] = o;
    }

    // ksum[d]: 4 segment partials of 8 t's each
    {
        const int d = tid & 63, q = tid >> 6;
        float s = 0.0f;
        #pragma unroll
        for (int i = q*8; i < q*8 + 8; i++) s += Ks[i*DD + d];
        seg[q*DD + d] = s;
    }
    __syncthreads();
    if (tid < DD) {
        g_k[(size_t)b*DD + tid] =
            seg[tid] + seg[DD + tid] + seg[2*DD + tid] + seg[3*DD + tid];
    }
}

// ---------------------------------------------------------------------------
// Kernel B: in-place exclusive prefix over the 64 chunks.
// blocks [0, NH*DD): one (nh,d) row of S, 64 threads (one per m).
// blocks [NH*DD, NH*DD+NH): g_k rows. Only 64 threads -> 64 val regs OK.
// ---------------------------------------------------------------------------
__global__ void __launch_bounds__(64) prefix_kernel()
{
    const int blk = blockIdx.x;
    const int tid = threadIdx.x;

    if (blk < NH*DD) {
        const int nh = blk >> 6, d = blk & 63;
        float* base = g_S + ((size_t)nh*CC*DD + d)*MM + tid;
        float run = 0.0f;
        #pragma unroll
        for (int half = 0; half < 2; half++) {
            float val[CC/2];
            #pragma unroll
            for (int j = 0; j < CC/2; j++)
                val[j] = base[(size_t)(half*(CC/2) + j)*DD*MM];
            #pragma unroll
            for (int j = 0; j < CC/2; j++) {
                base[(size_t)(half*(CC/2) + j)*DD*MM] = run;
                run += val[j];
            }
        }
    } else {
        const int nh = blk - NH*DD;
        float* base = g_k + (size_t)nh*CC*DD + tid;
        float run = 0.0f;
        #pragma unroll
        for (int half = 0; half < 2; half++) {
            float val[CC/2];
            #pragma unroll
            for (int j = 0; j < CC/2; j++)
                val[j] = base[(half*(CC/2) + j)*DD];
            #pragma unroll
            for (int j = 0; j < CC/2; j++) {
                base[(half*(CC/2) + j)*DD] = run;
                run += val[j];
            }
        }
    }
}

// ---------------------------------------------------------------------------
// Kernel C: in-chunk sequential scan, register-resident state.
// 1024 blocks, 256 threads. Thread (dq,m) owns d = 16*jj + 4*dq + e.
// ---------------------------------------------------------------------------
#define ZP_STRIDE 65
__global__ void __launch_bounds__(256) scan_kernel(
    const float* __restrict__ queries, const float* __restrict__ keys,
    const float* __restrict__ values, float* __restrict__ out)
{
    __shared__ float Qs[T*DD];            // 8 KB
    __shared__ float Ks[T*DD];            // 8 KB
    __shared__ float Vs[T*MM];            // 8 KB
    __shared__ float zp[T*ZP_STRIDE];     // 8.3 KB (padded products)
    __shared__ float seg[4*DD];           // 1 KB
    __shared__ float zinv[T];
    __shared__ float kpre[DD];

    const int b   = blockIdx.x;
    const int nh  = b / CC, c = b % CC;
    const int n   = nh / HH, h = nh % HH;
    const int tid = threadIdx.x;

    const float4* qg = (const float4*)queries;
    const float4* kg = (const float4*)keys;
    const float4* vg = (const float4*)values;
    float4* Qs4 = (float4*)Qs;
    float4* Ks4 = (float4*)Ks;
    float4* Vs4 = (float4*)Vs;

    #pragma unroll
    for (int f = tid; f < T*DD/4; f += 256) {
        int t = f >> 4, d4 = f & 15;
        int gi = ((n*LL + c*T + t)*HH + h)*(DD/4) + d4;
        Qs4[f] = phi4(qg[gi]);
        Ks4[f] = phi4(kg[gi]);
        Vs4[f] = vg[gi];
    }
    if (tid < DD) kpre[tid] = g_k[(size_t)b*DD + tid];
    __syncthreads();

    // --- z phase: segmented cumsum of K along i (4 segs of 8), fused Q product ---
    {
        const int d = tid & 63, q = tid >> 6;
        float s = 0.0f;
        #pragma unroll
        for (int i = q*8; i < q*8 + 8; i++) s += Ks[i*DD + d];
        seg[q*DD + d] = s;
        __syncthreads();
        float kc = kpre[d];
        #pragma unroll
        for (int r = 0; r < 4; r++) if (r < q) kc += seg[r*DD + d];
        #pragma unroll
        for (int i = q*8; i < q*8 + 8; i++) {
            kc += Ks[i*DD + d];
            zp[i*ZP_STRIDE + d] = Qs[i*DD + d] * kc;   // stride-65: conflict-free
        }
    }
    __syncthreads();
    // reduce zp over d: 256 threads = 32 i x 8 d-groups of 8
    {
        const int i = tid >> 3, dg = tid & 7;
        float z = 0.0f;
        #pragma unroll
        for (int e = 0; e < 8; e++) z += zp[i*ZP_STRIDE + dg*8 + e];
        z += __shfl_xor_sync(0xffffffffu, z, 1);
        z += __shfl_xor_sync(0xffffffffu, z, 2);
        z += __shfl_xor_sync(0xffffffffu, z, 4);
        if (dg == 0) zinv[i] = 1.0f / (z + EPSF);
    }
    __syncthreads();

    // --- main scan: thread (dq, m) owns S[16*jj+4*dq+e][m] ---
    const int dq = tid & 3;
    const int m  = tid >> 2;

    float acc[16];
    const float* Sp = &g_S[(size_t)b * DD * MM];
    #pragma unroll
    for (int jj = 0; jj < 4; jj++)
        #pragma unroll
        for (int e = 0; e < 4; e++)
            acc[jj*4+e] = Sp[(16*jj + 4*dq + e)*MM + m];

    const float4* K4 = (const float4*)Ks;
    const float4* Q4 = (const float4*)Qs;
    const int obase = ((n*LL + c*T)*HH + h)*MM + m;

    #pragma unroll 2
    for (int i = 0; i < T; i++) {
        float vv = Vs[i*MM + m];
        float p0 = 0.f, p1 = 0.f, p2 = 0.f, p3 = 0.f;
        {
            float4 k4 = K4[i*16 + 0*4 + dq];
            float4 q4 = Q4[i*16 + 0*4 + dq];
            acc[ 0] += k4.x*vv; p0 += q4.x*acc[ 0];
            acc[ 1] += k4.y*vv; p0 += q4.y*acc[ 1];
            acc[ 2] += k4.z*vv; p0 += q4.z*acc[ 2];
            acc[ 3] += k4.w*vv; p0 += q4.w*acc[ 3];
        }
        {
            float4 k4 = K4[i*16 + 1*4 + dq];
            float4 q4 = Q4[i*16 + 1*4 + dq];
            acc[ 4] += k4.x*vv; p1 += q4.x*acc[ 4];
            acc[ 5] += k4.y*vv; p1 += q4.y*acc[ 5];
            acc[ 6] += k4.z*vv; p1 += q4.z*acc[ 6];
            acc[ 7] += k4.w*vv; p1 += q4.w*acc[ 7];
        }
        {
            float4 k4 = K4[i*16 + 2*4 + dq];
            float4 q4 = Q4[i*16 + 2*4 + dq];
            acc[ 8] += k4.x*vv; p2 += q4.x*acc[ 8];
            acc[ 9] += k4.y*vv; p2 += q4.y*acc[ 9];
            acc[10] += k4.z*vv; p2 += q4.z*acc[10];
            acc[11] += k4.w*vv; p2 += q4.w*acc[11];
        }
        {
            float4 k4 = K4[i*16 + 3*4 + dq];
            float4 q4 = Q4[i*16 + 3*4 + dq];
            acc[12] += k4.x*vv; p3 += q4.x*acc[12];
            acc[13] += k4.y*vv; p3 += q4.y*acc[13];
            acc[14] += k4.z*vv; p3 += q4.z*acc[14];
            acc[15] += k4.w*vv; p3 += q4.w*acc[15];
        }
        float p = (p0 + p1) + (p2 + p3);
        p += __shfl_xor_sync(0xffffffffu, p, 1);   // reduce over dq
        p += __shfl_xor_sync(0xffffffffu, p, 2);
        if (dq == 0)
            out[obase + i*HH*MM] = p * zinv[i];
    }
}

// ---------------------------------------------------------------------------
extern "C" void kernel_launch(void* const* d_in, const int* in_sizes, int n_in,
                              void* d_out, int out_size)
{
    const float* queries = (const float*)d_in[0];
    const float* keys    = (const float*)d_in[1];
    const float* values  = (const float*)d_in[2];
    float* out = (float*)d_out;

    chunk_sums_kernel<<<NBLK, 256>>>(keys, values);
    prefix_kernel<<<NH*DD + NH, 64>>>();
    scan_kernel<<<NBLK, 256>>>(queries, keys, values, out);
}

// round 10
// speedup vs baseline: 1.9113x; 1.0171x over previous
#include <cuda_runtime.h>
#include <math.h>

// Problem shape (fixed by setup_inputs)
#define NB 2
#define LL 2048
#define HH 8
#define DD 64
#define MM 64
#define NH (NB*HH)          // 16
#define T  32               // chunk length
#define CC (LL/T)           // 64 chunks
#define NBLK (NH*CC)        // 1024
#define EPSF 1e-6f

typedef unsigned long long ull;

// Scratch (static device arrays — no runtime alloc)
__device__ float g_S[(size_t)NH*CC*DD*MM];   // 16.8 MB
__device__ float g_k[(size_t)NH*CC*DD];      // 256 KB

__device__ __forceinline__ float phi(float x) {
    return x > 0.0f ? x + 1.0f : expf(x);   // elu(x)+1
}
__device__ __forceinline__ float4 phi4(float4 a) {
    return make_float4(phi(a.x), phi(a.y), phi(a.z), phi(a.w));
}

// ---- packed f32x2 helpers (FFMA2: ptxas never emits it; PTX does) ----
__device__ __forceinline__ ull pack2(float lo, float hi) {
    ull r; asm("mov.b64 %0, {%1, %2};" : "=l"(r) : "f"(lo), "f"(hi)); return r;
}
__device__ __forceinline__ void unpack2(ull v, float& lo, float& hi) {
    asm("mov.b64 {%0, %1}, %2;" : "=f"(lo), "=f"(hi) : "l"(v));
}
__device__ __forceinline__ ull fma2(ull a, ull b, ull c) {
    ull d; asm("fma.rn.f32x2 %0, %1, %2, %3;" : "=l"(d) : "l"(a), "l"(b), "l"(c));
    return d;
}

// ---------------------------------------------------------------------------
// Kernel A: chunk sums  Sc[d][m] = sum_t phi(k)[t][d] * v[t][m]
// 1024 blocks, 256 threads. 4x4 tile, inner loop in FFMA2 (8 per t).
// ---------------------------------------------------------------------------
__global__ void __launch_bounds__(256) chunk_sums_kernel(
    const float* __restrict__ keys, const float* __restrict__ values)
{
    __shared__ __align__(16) float Ks[T*DD];   // 8 KB
    __shared__ __align__(16) float Vs[T*MM];   // 8 KB
    __shared__ float seg[4*DD];                // 1 KB

    const int b   = blockIdx.x;
    const int nh  = b / CC, c = b % CC;
    const int n   = nh / HH, h = nh % HH;
    const int tid = threadIdx.x;

    const float4* kg = (const float4*)keys;
    const float4* vg = (const float4*)values;
    float4* Ks4 = (float4*)Ks;
    float4* Vs4 = (float4*)Vs;

    #pragma unroll
    for (int f = tid; f < T*DD/4; f += 256) {
        int t = f >> 4, d4 = f & 15;
        int gi = ((n*LL + c*T + t)*HH + h)*(DD/4) + d4;
        Ks4[f] = phi4(kg[gi]);
        Vs4[f] = vg[gi];
    }
    __syncthreads();

    const int td = tid >> 4;    // 0..15
    const int tm = tid & 15;    // 0..15

    ull acc2[8];
    #pragma unroll
    for (int j = 0; j < 8; j++) acc2[j] = 0ull;

    const float4* K4 = (const float4*)Ks;
    #pragma unroll 4
    for (int t = 0; t < T; t++) {
        float4 k4 = K4[t*16 + td];
        const ull* Vp = (const ull*)&Vs[t*MM + 4*tm];
        ull v01 = Vp[0], v23 = Vp[1];
        ull kx = pack2(k4.x, k4.x);
        ull ky = pack2(k4.y, k4.y);
        ull kz = pack2(k4.z, k4.z);
        ull kw = pack2(k4.w, k4.w);
        acc2[0] = fma2(kx, v01, acc2[0]);  acc2[1] = fma2(kx, v23, acc2[1]);
        acc2[2] = fma2(ky, v01, acc2[2]);  acc2[3] = fma2(ky, v23, acc2[3]);
        acc2[4] = fma2(kz, v01, acc2[4]);  acc2[5] = fma2(kz, v23, acc2[5]);
        acc2[6] = fma2(kw, v01, acc2[6]);  acc2[7] = fma2(kw, v23, acc2[7]);
    }

    float* So = &g_S[(size_t)b * DD * MM];
    #pragma unroll
    for (int r = 0; r < 4; r++) {
        float4 o;
        unpack2(acc2[r*2+0], o.x, o.y);
        unpack2(acc2[r*2+1], o.z, o.w);
        *(float4*)&So[(4*td + r)*MM + 4*tm] = o;
    }

    // ksum[d]: 4 segment partials of 8 t's each
    {
        const int d = tid & 63, q = tid >> 6;
        float s = 0.0f;
        #pragma unroll
        for (int i = q*8; i < q*8 + 8; i++) s += Ks[i*DD + d];
        seg[q*DD + d] = s;
    }
    __syncthreads();
    if (tid < DD) {
        g_k[(size_t)b*DD + tid] =
            seg[tid] + seg[DD + tid] + seg[2*DD + tid] + seg[3*DD + tid];
    }
}

// ---------------------------------------------------------------------------
// Kernel B: in-place exclusive prefix over the 64 chunks.
// ---------------------------------------------------------------------------
__global__ void __launch_bounds__(64) prefix_kernel()
{
    const int blk = blockIdx.x;
    const int tid = threadIdx.x;

    if (blk < NH*DD) {
        const int nh = blk >> 6, d = blk & 63;
        float* base = g_S + ((size_t)nh*CC*DD + d)*MM + tid;
        float run = 0.0f;
        #pragma unroll
        for (int half = 0; half < 2; half++) {
            float val[CC/2];
            #pragma unroll
            for (int j = 0; j < CC/2; j++)
                val[j] = base[(size_t)(half*(CC/2) + j)*DD*MM];
            #pragma unroll
            for (int j = 0; j < CC/2; j++) {
                base[(size_t)(half*(CC/2) + j)*DD*MM] = run;
                run += val[j];
            }
        }
    } else {
        const int nh = blk - NH*DD;
        float* base = g_k + (size_t)nh*CC*DD + tid;
        float run = 0.0f;
        #pragma unroll
        for (int half = 0; half < 2; half++) {
            float val[CC/2];
            #pragma unroll
            for (int j = 0; j < CC/2; j++)
                val[j] = base[(half*(CC/2) + j)*DD];
            #pragma unroll
            for (int j = 0; j < CC/2; j++) {
                base[(half*(CC/2) + j)*DD] = run;
                run += val[j];
            }
        }
    }
}

// ---------------------------------------------------------------------------
// Kernel C: in-chunk sequential scan, register-resident packed state.
// 1024 blocks, 256 threads. Thread (dq,m) owns d = 16*jj + 4*dq + e;
// state + dot partials in f32x2 pairs (16 FFMA2 per step).
// ---------------------------------------------------------------------------
#define ZP_STRIDE 65
__global__ void __launch_bounds__(256) scan_kernel(
    const float* __restrict__ queries, const float* __restrict__ keys,
    const float* __restrict__ values, float* __restrict__ out)
{
    __shared__ __align__(16) float Qs[T*DD];            // 8 KB
    __shared__ __align__(16) float Ks[T*DD];            // 8 KB
    __shared__ __align__(16) float Vs[T*MM];            // 8 KB
    __shared__ float zp[T*ZP_STRIDE];                   // 8.3 KB
    __shared__ float seg[4*DD];                         // 1 KB
    __shared__ float zinv[T];
    __shared__ float kpre[DD];

    const int b   = blockIdx.x;
    const int nh  = b / CC, c = b % CC;
    const int n   = nh / HH, h = nh % HH;
    const int tid = threadIdx.x;

    const float4* qg = (const float4*)queries;
    const float4* kg = (const float4*)keys;
    const float4* vg = (const float4*)values;
    float4* Qs4 = (float4*)Qs;
    float4* Ks4 = (float4*)Ks;
    float4* Vs4 = (float4*)Vs;

    #pragma unroll
    for (int f = tid; f < T*DD/4; f += 256) {
        int t = f >> 4, d4 = f & 15;
        int gi = ((n*LL + c*T + t)*HH + h)*(DD/4) + d4;
        Qs4[f] = phi4(qg[gi]);
        Ks4[f] = phi4(kg[gi]);
        Vs4[f] = vg[gi];
    }
    if (tid < DD) kpre[tid] = g_k[(size_t)b*DD + tid];
    __syncthreads();

    // --- z phase: segmented cumsum of K along i (4 segs of 8), fused Q product ---
    {
        const int d = tid & 63, q = tid >> 6;
        float s = 0.0f;
        #pragma unroll
        for (int i = q*8; i < q*8 + 8; i++) s += Ks[i*DD + d];
        seg[q*DD + d] = s;
        __syncthreads();
        float kc = kpre[d];
        #pragma unroll
        for (int r = 0; r < 4; r++) if (r < q) kc += seg[r*DD + d];
        #pragma unroll
        for (int i = q*8; i < q*8 + 8; i++) {
            kc += Ks[i*DD + d];
            zp[i*ZP_STRIDE + d] = Qs[i*DD + d] * kc;   // stride-65: conflict-free
        }
    }
    __syncthreads();
    // reduce zp over d: 256 threads = 32 i x 8 d-groups of 8
    {
        const int i = tid >> 3, dg = tid & 7;
        float z = 0.0f;
        #pragma unroll
        for (int e = 0; e < 8; e++) z += zp[i*ZP_STRIDE + dg*8 + e];
        z += __shfl_xor_sync(0xffffffffu, z, 1);
        z += __shfl_xor_sync(0xffffffffu, z, 2);
        z += __shfl_xor_sync(0xffffffffu, z, 4);
        if (dg == 0) zinv[i] = 1.0f / (z + EPSF);
    }
    __syncthreads();

    // --- main scan: thread (dq, m) owns S[16*jj+4*dq+e][m], packed pairs ---
    const int dq = tid & 3;
    const int m  = tid >> 2;

    ull acc2[8];
    const float* Sp = &g_S[(size_t)b * DD * MM];
    #pragma unroll
    for (int jj = 0; jj < 4; jj++) {
        int d0 = 16*jj + 4*dq;
        acc2[jj*2+0] = pack2(Sp[(d0+0)*MM + m], Sp[(d0+1)*MM + m]);
        acc2[jj*2+1] = pack2(Sp[(d0+2)*MM + m], Sp[(d0+3)*MM + m]);
    }

    const int obase = ((n*LL + c*T)*HH + h)*MM + m;

    #pragma unroll 2
    for (int i = 0; i < T; i++) {
        float vv = Vs[i*MM + m];
        ull vv2 = pack2(vv, vv);
        ull pa = 0ull, pb = 0ull;
        #pragma unroll
        for (int jj = 0; jj < 4; jj++) {
            const ull* Kp = (const ull*)&Ks[i*DD + 16*jj + 4*dq];
            const ull* Qp = (const ull*)&Qs[i*DD + 16*jj + 4*dq];
            ull k01 = Kp[0], k23 = Kp[1];
            ull q01 = Qp[0], q23 = Qp[1];
            acc2[jj*2+0] = fma2(k01, vv2, acc2[jj*2+0]);
            pa           = fma2(q01, acc2[jj*2+0], pa);
            acc2[jj*2+1] = fma2(k23, vv2, acc2[jj*2+1]);
            pb           = fma2(q23, acc2[jj*2+1], pb);
        }
        float a0, a1, b0, b1;
        unpack2(pa, a0, a1);
        unpack2(pb, b0, b1);
        float p = (a0 + a1) + (b0 + b1);
        p += __shfl_xor_sync(0xffffffffu, p, 1);   // reduce over dq
        p += __shfl_xor_sync(0xffffffffu, p, 2);
        if (dq == 0)
            out[obase + i*HH*MM] = p * zinv[i];
    }
}

// ---------------------------------------------------------------------------
extern "C" void kernel_launch(void* const* d_in, const int* in_sizes, int n_in,
                              void* d_out, int out_size)
{
    const float* queries = (const float*)d_in[0];
    const float* keys    = (const float*)d_in[1];
    const float* values  = (const float*)d_in[2];
    float* out = (float*)d_out;

    chunk_sums_kernel<<<NBLK, 256>>>(keys, values);
    prefix_kernel<<<NH*DD + NH, 64>>>();
    scan_kernel<<<NBLK, 256>>>(queries, keys, values, out);
}